// round 8
// baseline (speedup 1.0000x reference)
#include <cuda_runtime.h>

#define NSAMP 16384
#define PTS   20
#define DIM   128
#define KNN   5
#define NANCH (NSAMP * PTS)
#define EDGES (NANCH * KNN)

#define SPB 4
#define NTH 96                        // 3 warps; first 80 threads compute
#define RSTRIDE 132                   // words/row: conflict-free 16B-quad access
#define SAMP_STRIDE (PTS * RSTRIDE)   // 2640 words
#define SMEM_X (SPB * SAMP_STRIDE)    // 10560 words
#define D2S 21                        // d2 matrix row stride (conflict-free gather)
#define D2WORDS (PTS * D2S)           // 420 words per sample
#define SMEM_FLOATS (SMEM_X + SPB * D2WORDS)   // 12240 words = 48,960 B <= 48 KB

__device__ __forceinline__ void fma2(unsigned long long &acc,
                                     unsigned long long a,
                                     unsigned long long b) {
    asm("fma.rn.f32x2 %0, %1, %2, %0;" : "+l"(acc) : "l"(a), "l"(b));
}

// (a0+a1) + (a2+a3): summation order identical to rounds 6/7
__device__ __forceinline__ float chainsum(unsigned long long acc01,
                                          unsigned long long acc23) {
    float2 lo = *reinterpret_cast<float2*>(&acc01);
    float2 hi = *reinterpret_cast<float2*>(&acc23);
    return (lo.x + lo.y) + (hi.x + hi.y);
}

__global__ void __launch_bounds__(NTH, 4)
knn_kernel(const float* __restrict__ x, float* __restrict__ out, int cap) {
    __shared__ __align__(16) float sm[SMEM_FLOATS];

    const int tid = threadIdx.x;
    const int bs0 = blockIdx.x * SPB;

    // ---- Stage 4 samples gmem -> smem (coalesced float4) ----
    {
        const float4* xin = reinterpret_cast<const float4*>(x)
                          + (size_t)bs0 * (PTS * DIM / 4);
        #pragma unroll
        for (int t = tid; t < SPB * PTS * (DIM / 4); t += NTH) {
            int rc  = t >> 5;
            int e   = t & 31;
            int s   = rc / PTS;
            int row = rc - s * PTS;
            float4 v = xin[(size_t)rc * 32 + e];
            *reinterpret_cast<float4*>(&sm[s * SAMP_STRIDE + row * RSTRIDE + e * 4]) = v;
        }
    }
    __syncthreads();

    const bool active = (tid < SPB * PTS);
    const int s = active ? (tid / PTS) : 0;
    const int p = active ? (tid - s * PTS) : 0;
    float* d2mat = &sm[SMEM_X + s * D2WORDS];

    // ---- Own row -> regs (f32x2 pairs); norm -> d2 diagonal ----
    unsigned long long xp[DIM / 2];
    float sqp = 0.0f;
    if (active) {
        const ulonglong2* xrow =
            reinterpret_cast<const ulonglong2*>(&sm[s * SAMP_STRIDE + p * RSTRIDE]);
        unsigned long long n01 = 0ull, n23 = 0ull;
        #pragma unroll
        for (int e = 0; e < DIM / 4; e++) {
            ulonglong2 v = xrow[e];
            xp[2 * e]     = v.x;
            xp[2 * e + 1] = v.y;
            fma2(n01, v.x, v.x);
            fma2(n23, v.y, v.y);
        }
        sqp = chainsum(n01, n23);
        d2mat[p * D2S + p] = sqp;           // norm on the (unused) diagonal
    }
    __syncthreads();

    // ---- Pair phase: each unordered pair computed once (j = 1..10) ----
    if (active) {
        const float* sbase = &sm[s * SAMP_STRIDE];
        #pragma unroll 1
        for (int j = 1; j <= 10; j++) {
            int q = p + j; if (q >= PTS) q -= PTS;
            if (j == 10 && p >= 10) continue;        // offset-10 pairs: dedupe

            const ulonglong2* xq =
                reinterpret_cast<const ulonglong2*>(sbase + q * RSTRIDE);
            unsigned long long a01 = 0ull, a23 = 0ull;
            #pragma unroll
            for (int e = 0; e < DIM / 4; e++) {
                ulonglong2 v = xq[e];
                fma2(a01, xp[2 * e],     v.x);
                fma2(a23, xp[2 * e + 1], v.y);
            }
            const float dot = chainsum(a01, a23);
            const float sqq = d2mat[q * D2S + q];
            const float d2  = fmaxf(sqp + sqq - 2.0f * dot, 0.0f);  // ref clamp
            d2mat[p * D2S + q] = d2;      // dot/sum commutative -> bit-identical
            d2mat[q * D2S + p] = d2;      // to computing each direction separately
        }
    }
    __syncthreads();
    if (!active) return;

    // ---- Sort phase: exact u64-keyed branchless top-5 over row p ----
    unsigned long long keys[KNN];
    #pragma unroll
    for (int m = 0; m < KNN; m++) keys[m] = 0xFFFFFFFFFFFFFFFFull;

    const float* myrow = &d2mat[p * D2S];
    #pragma unroll
    for (int q = 0; q < PTS; q++) {
        float d2 = myrow[q];
        unsigned long long key = (q == p)
            ? 0xFFFFFFFFFFFFFFFFull
            : (((unsigned long long)__float_as_uint(d2) << 32) | (unsigned)q);
        #pragma unroll
        for (int m = 0; m < KNN; m++) {
            unsigned long long lo = (keys[m] < key) ? keys[m] : key;
            unsigned long long hi = (keys[m] < key) ? key : keys[m];
            keys[m] = lo;
            key = hi;
        }
    }

    // ---- Emit float32: U in [0, EDGES), V in [EDGES, 2*EDGES) ----
    const int w  = (bs0 + s) * PTS + p;
    const int ob = w * KNN;
    const float pf = (float)p;
    #pragma unroll
    for (int r = 0; r < KNN; r++) {
        int iu = ob + r;
        int iv = EDGES + ob + r;
        if (iu < cap) out[iu] = pf;
        if (iv < cap) out[iv] = (float)(int)(keys[r] & 0xFFFFFFFFull);
    }
}

extern "C" void kernel_launch(void* const* d_in, const int* in_sizes, int n_in,
                              void* d_out, int out_size) {
    const float* x = (const float*)d_in[0];
    float* out = (float*)d_out;

    int cap = 2 * EDGES;
    if (out_size > 0 && out_size < 2 * EDGES) cap = out_size;

    const int grid = NSAMP / SPB;    // 4096
    knn_kernel<<<grid, NTH>>>(x, out, cap);
}

// round 9
// speedup vs baseline: 1.0515x; 1.0515x over previous
#include <cuda_runtime.h>

#define NSAMP 16384
#define PTS   20
#define DIM   128
#define KNN   5
#define NANCH (NSAMP * PTS)
#define EDGES (NANCH * KNN)

#define SPB 4
#define NTH 96                        // 3 warps; first 80 threads compute
#define RSTRIDE 132                   // words/row
#define SAMP_STRIDE (PTS * RSTRIDE)   // 2640 words
#define SMEM_X (SPB * SAMP_STRIDE)    // 10560 words
#define SMEM_FLOATS (SMEM_X + SPB * PTS)  // + norms = 42,560 B

__device__ __forceinline__ void fma2(unsigned long long &acc,
                                     unsigned long long a,
                                     unsigned long long b) {
    asm("fma.rn.f32x2 %0, %1, %2, %0;" : "+l"(acc) : "l"(a), "l"(b));
}

// (a0+a1) + (a2+a3): summation order identical to round 7
__device__ __forceinline__ float chainsum(unsigned long long acc01,
                                          unsigned long long acc23) {
    float2 lo = *reinterpret_cast<float2*>(&acc01);
    float2 hi = *reinterpret_cast<float2*>(&acc23);
    return (lo.x + lo.y) + (hi.x + hi.y);
}

__device__ __forceinline__ void key_insert(unsigned long long keys[KNN],
                                           unsigned long long key) {
    #pragma unroll
    for (int m = 0; m < KNN; m++) {
        unsigned long long lo = (keys[m] < key) ? keys[m] : key;
        unsigned long long hi = (keys[m] < key) ? key : keys[m];
        keys[m] = lo;
        key = hi;
    }
}

__global__ void __launch_bounds__(NTH, 4)
knn_kernel(const float* __restrict__ x, float* __restrict__ out, int cap) {
    __shared__ __align__(16) float sm[SMEM_FLOATS];
    float* snorm = &sm[SMEM_X];

    const int tid = threadIdx.x;
    const int bs0 = blockIdx.x * SPB;

    // ---- Stage 4 samples gmem -> smem (coalesced float4) ----
    {
        const float4* xin = reinterpret_cast<const float4*>(x)
                          + (size_t)bs0 * (PTS * DIM / 4);
        #pragma unroll
        for (int t = tid; t < SPB * PTS * (DIM / 4); t += NTH) {
            int rc  = t >> 5;
            int e   = t & 31;
            int s   = rc / PTS;
            int row = rc - s * PTS;
            float4 v = xin[(size_t)rc * 32 + e];
            *reinterpret_cast<float4*>(&sm[s * SAMP_STRIDE + row * RSTRIDE + e * 4]) = v;
        }
    }
    __syncthreads();

    const bool active = (tid < SPB * PTS);
    const int s = active ? (tid / PTS) : 0;
    const int p = active ? (tid - s * PTS) : 0;

    // ---- Own row -> regs (f32x2 pairs); norm with identical chains ----
    unsigned long long xp[DIM / 2];
    float sqp = 0.0f;
    if (active) {
        const ulonglong2* xrow =
            reinterpret_cast<const ulonglong2*>(&sm[s * SAMP_STRIDE + p * RSTRIDE]);
        unsigned long long n01 = 0ull, n23 = 0ull;
        #pragma unroll
        for (int e = 0; e < DIM / 4; e++) {
            ulonglong2 v = xrow[e];
            xp[2 * e]     = v.x;
            xp[2 * e + 1] = v.y;
            fma2(n01, v.x, v.x);
            fma2(n23, v.y, v.y);
        }
        sqp = chainsum(n01, n23);
        snorm[s * PTS + p] = sqp;
    }
    __syncthreads();
    if (!active) return;

    // ---- Stream candidates 2-at-a-time (q, q+10): 4 independent FMA2 chains ----
    unsigned long long keys[KNN];
    #pragma unroll
    for (int m = 0; m < KNN; m++) keys[m] = 0xFFFFFFFFFFFFFFFFull;

    const float* sbase = &sm[s * SAMP_STRIDE];
    #pragma unroll 1
    for (int q = 0; q < 10; q++) {
        const ulonglong2* xq0 =
            reinterpret_cast<const ulonglong2*>(sbase + q * RSTRIDE);
        const ulonglong2* xq1 =
            reinterpret_cast<const ulonglong2*>(sbase + (q + 10) * RSTRIDE);
        unsigned long long a01 = 0ull, a23 = 0ull;   // chains for row q
        unsigned long long b01 = 0ull, b23 = 0ull;   // chains for row q+10
        #pragma unroll
        for (int e = 0; e < DIM / 4; e++) {
            ulonglong2 v0 = xq0[e];                   // broadcast loads
            ulonglong2 v1 = xq1[e];
            fma2(a01, xp[2 * e],     v0.x);
            fma2(b01, xp[2 * e],     v1.x);
            fma2(a23, xp[2 * e + 1], v0.y);
            fma2(b23, xp[2 * e + 1], v1.y);
        }
        const float dot0 = chainsum(a01, a23);
        const float dot1 = chainsum(b01, b23);
        const float sqq0 = snorm[s * PTS + q];
        const float sqq1 = snorm[s * PTS + q + 10];
        const float d20  = fmaxf(sqp + sqq0 - 2.0f * dot0, 0.0f);  // ref clamp
        const float d21  = fmaxf(sqp + sqq1 - 2.0f * dot1, 0.0f);

        unsigned long long k0 = (q == p)
            ? 0xFFFFFFFFFFFFFFFFull
            : (((unsigned long long)__float_as_uint(d20) << 32) | (unsigned)q);
        unsigned long long k1 = (q + 10 == p)
            ? 0xFFFFFFFFFFFFFFFFull
            : (((unsigned long long)__float_as_uint(d21) << 32) | (unsigned)(q + 10));
        key_insert(keys, k0);
        key_insert(keys, k1);
    }

    // ---- Emit float32: U in [0, EDGES), V in [EDGES, 2*EDGES) ----
    const int w  = (bs0 + s) * PTS + p;
    const int ob = w * KNN;
    const float pf = (float)p;
    #pragma unroll
    for (int r = 0; r < KNN; r++) {
        int iu = ob + r;
        int iv = EDGES + ob + r;
        if (iu < cap) out[iu] = pf;
        if (iv < cap) out[iv] = (float)(int)(keys[r] & 0xFFFFFFFFull);
    }
}

extern "C" void kernel_launch(void* const* d_in, const int* in_sizes, int n_in,
                              void* d_out, int out_size) {
    const float* x = (const float*)d_in[0];
    float* out = (float*)d_out;

    int cap = 2 * EDGES;
    if (out_size > 0 && out_size < 2 * EDGES) cap = out_size;

    const int grid = NSAMP / SPB;    // 4096
    knn_kernel<<<grid, NTH>>>(x, out, cap);
}

// round 10
// speedup vs baseline: 1.1451x; 1.0891x over previous
#include <cuda_runtime.h>

#define NSAMP 16384
#define PTS   20
#define DIM   128
#define KNN   5
#define NANCH (NSAMP * PTS)
#define EDGES (NANCH * KNN)

#define SPB 3
#define NTH 128                        // 4 warps; first 120 threads compute
#define ACT (SPB * PTS * 2)            // 120 = 3 samples x 20 anchors x 2 halves
#define RSTRIDE 136                    // [64 dims][4 pad][64 dims][4 pad]
#define HOFF 68                        // word offset of half 1 within a row
#define SAMP_STRIDE (PTS * RSTRIDE + 8)   // 2728 (mod 32 == 8: per-sample bank shift)
#define SMEM_X (SPB * SAMP_STRIDE)        // 8184 words
#define PDS 21                            // pd row stride (coprime with 32)
#define PD_PER_S (2 * PTS * PDS)          // 840 words
#define SMEM_FLOATS (SMEM_X + SPB * PD_PER_S)   // 10704 words = 42,816 B

__device__ __forceinline__ void fma2(unsigned long long &acc,
                                     unsigned long long a,
                                     unsigned long long b) {
    asm("fma.rn.f32x2 %0, %1, %2, %0;" : "+l"(acc) : "l"(a), "l"(b));
}

__device__ __forceinline__ float chainsum(unsigned long long acc01,
                                          unsigned long long acc23) {
    float2 lo = *reinterpret_cast<float2*>(&acc01);
    float2 hi = *reinterpret_cast<float2*>(&acc23);
    return (lo.x + lo.y) + (hi.x + hi.y);
}

__global__ void __launch_bounds__(NTH, 4)
knn_kernel(const float* __restrict__ x, float* __restrict__ out, int cap) {
    __shared__ __align__(16) float sm[SMEM_FLOATS];
    float* pd = &sm[SMEM_X];

    const int tid = threadIdx.x;
    const int bs0 = blockIdx.x * SPB;

    // ---- Stage up to 3 samples gmem -> smem (float4, split-row layout) ----
    {
        const float4* xin = reinterpret_cast<const float4*>(x)
                          + (size_t)bs0 * (PTS * DIM / 4);
        #pragma unroll
        for (int t = tid; t < SPB * PTS * (DIM / 4); t += NTH) {
            int rc  = t >> 5;                  // row 0..59
            int e   = t & 31;                  // float4 idx in row
            int s   = rc / PTS;
            int row = rc - s * PTS;
            if (bs0 + s < NSAMP) {
                float4 v = xin[(size_t)rc * 32 + e];
                int dest = s * SAMP_STRIDE + row * RSTRIDE + 4 * e + (e >= 16 ? 4 : 0);
                *reinterpret_cast<float4*>(&sm[dest]) = v;
            }
        }
    }
    __syncthreads();

    const bool active = (tid < ACT);
    const int s = active ? (tid / (2 * PTS)) : 0;
    const int r = active ? (tid - s * 2 * PTS) : 0;
    const int h = r / PTS;                      // half: 0 -> dims 0-63, 1 -> 64-127
    const int p = r - h * PTS;                  // anchor within sample
    const bool valid = active && (bs0 + s < NSAMP);

    // ---- Phase 2: partial dots over this half for all 20 candidates ----
    if (valid) {
        const float* base = &sm[s * SAMP_STRIDE];
        // own half-row -> registers (16 x LDS.128 = 64 regs)
        unsigned long long xp[32];
        {
            const ulonglong2* xrow =
                reinterpret_cast<const ulonglong2*>(base + p * RSTRIDE + h * HOFF);
            #pragma unroll
            for (int e = 0; e < 16; e++) {
                ulonglong2 v = xrow[e];
                xp[2 * e]     = v.x;
                xp[2 * e + 1] = v.y;
            }
        }
        float* pdrow = &pd[((s * 2 + h) * PTS + p) * PDS];
        #pragma unroll 2
        for (int q = 0; q < PTS; q++) {
            const ulonglong2* xq =
                reinterpret_cast<const ulonglong2*>(base + q * RSTRIDE + h * HOFF);
            unsigned long long a01 = 0ull, a23 = 0ull;
            #pragma unroll
            for (int e = 0; e < 16; e++) {
                ulonglong2 v = xq[e];            // 1-phase broadcast (disjoint banks)
                fma2(a01, xp[2 * e],     v.x);
                fma2(a23, xp[2 * e + 1], v.y);
            }
            pdrow[q] = chainsum(a01, a23);
        }
    }
    __syncthreads();

    // ---- Phase 3: h==0 threads assemble dots, select top-5, emit ----
    if (valid && h == 0) {
        const float* pd0 = &pd[((s * 2 + 0) * PTS + p) * PDS];
        const float* pd1 = &pd[((s * 2 + 1) * PTS + p) * PDS];
        const float* dg0 = &pd[(s * 2 + 0) * PTS * PDS];   // diag: dot(q,q) = ||q||^2
        const float* dg1 = &pd[(s * 2 + 1) * PTS * PDS];

        const float sqp = pd0[p] + pd1[p];

        unsigned long long keys[KNN];
        #pragma unroll
        for (int m = 0; m < KNN; m++) keys[m] = 0xFFFFFFFFFFFFFFFFull;

        #pragma unroll
        for (int q = 0; q < PTS; q++) {
            const float dot = pd0[q] + pd1[q];
            const float sqq = dg0[q * PDS + q] + dg1[q * PDS + q];
            const float d2  = fmaxf(sqp + sqq - 2.0f * dot, 0.0f);  // ref clamp
            unsigned long long key = (q == p)
                ? 0xFFFFFFFFFFFFFFFFull
                : (((unsigned long long)__float_as_uint(d2) << 32) | (unsigned)q);
            #pragma unroll
            for (int m = 0; m < KNN; m++) {
                unsigned long long lo = (keys[m] < key) ? keys[m] : key;
                unsigned long long hi = (keys[m] < key) ? key : keys[m];
                keys[m] = lo;
                key = hi;
            }
        }

        const int w  = (bs0 + s) * PTS + p;
        const int ob = w * KNN;
        const float pf = (float)p;
        #pragma unroll
        for (int rr = 0; rr < KNN; rr++) {
            int iu = ob + rr;
            int iv = EDGES + ob + rr;
            if (iu < cap) out[iu] = pf;
            if (iv < cap) out[iv] = (float)(int)(keys[rr] & 0xFFFFFFFFull);
        }
    }
}

extern "C" void kernel_launch(void* const* d_in, const int* in_sizes, int n_in,
                              void* d_out, int out_size) {
    const float* x = (const float*)d_in[0];
    float* out = (float*)d_out;

    int cap = 2 * EDGES;
    if (out_size > 0 && out_size < 2 * EDGES) cap = out_size;

    const int grid = (NSAMP + SPB - 1) / SPB;   // 5462
    knn_kernel<<<grid, NTH>>>(x, out, cap);
}